// round 1
// baseline (speedup 1.0000x reference)
#include <cuda_runtime.h>
#include <cuda_bf16.h>
#include <math.h>

// Problem constants
#define Bq 256      // sentences (batch for LSTMs, sequence for CRF)
#define Tt 128      // words per sentence
#define Ff 768      // feature size
#define HH 256      // word LSTM hidden
#define G4 1024     // 4*HH
#define H2 512      // 2*HH (sentence LSTM hidden)
#define G8 2048     // 4*H2
#define NC 16       // num classes

#define GXR_OFF 33554432   // 256*128*1024

// ---------------- scratch (static device memory; no allocations) ------------
__device__ float g_big[67108864];          // gx_f | gx_r, later reused as gx_s (256MB)
__device__ float g_hcat[Bq * Tt * H2];     // [B][T][512] word BiLSTM outputs (64MB)
__device__ float g_whhTf[HH * G4];         // w_hh_f transposed: [k][j]
__device__ float g_whhTr[HH * G4];
__device__ float g_whhTs[H2 * G8];
__device__ float g_hw[2][2][Bq][HH];       // word h state [dir][buf][b][n]
__device__ float g_hs[2][Bq][H2];          // sentence h state [buf][b][n]

__device__ unsigned g_bar_cnt = 0;
__device__ unsigned g_bar_gen = 0;

// software grid barrier: all CTAs guaranteed co-resident (grid <= 148, 1 CTA/SM fits)
__device__ __forceinline__ void grid_barrier(unsigned ncta) {
    __syncthreads();
    if (threadIdx.x == 0) {
        volatile unsigned* genp = &g_bar_gen;
        unsigned gen = *genp;
        __threadfence();
        if (atomicAdd(&g_bar_cnt, 1u) == ncta - 1u) {
            atomicExch(&g_bar_cnt, 0u);
            __threadfence();
            atomicExch(&g_bar_gen, gen + 1u);
        } else {
            while (*genp == gen) { }
        }
        __threadfence();
    }
    __syncthreads();
}

// ---------------- transpose: in [R][C] -> out [C][R] ------------------------
__global__ void transpose_kernel(const float* __restrict__ in, float* __restrict__ out,
                                 int R, int C) {
    int idx = blockIdx.x * blockDim.x + threadIdx.x;
    if (idx < R * C) {
        int r = idx / C, c = idx - r * C;
        out[c * R + r] = in[idx];
    }
}

// ---------------- fp32 GEMM: C[m][n] = sum_k A[m][k]*W[n][k] + bias[n] ------
// BM=BN=128, BK=8, 256 threads, 8x8 per thread.
__global__ void __launch_bounds__(256) sgemm_bias(
    const float* __restrict__ A, const float* __restrict__ W,
    const float* __restrict__ bias, float* __restrict__ C,
    int M, int N, int K)
{
    __shared__ float As[8][128];
    __shared__ float Bs[8][128];
    int tid = threadIdx.x;
    int tx = tid & 15, ty = tid >> 4;
    const float* Ab = A + (size_t)blockIdx.y * 128 * K;
    const float* Wb = W + (size_t)blockIdx.x * 128 * K;
    int lrow = tid >> 1;
    int lcol = (tid & 1) << 2;

    float acc[8][8];
#pragma unroll
    for (int i = 0; i < 8; i++)
#pragma unroll
        for (int j = 0; j < 8; j++) acc[i][j] = 0.f;

    for (int k0 = 0; k0 < K; k0 += 8) {
        float4 av = *(const float4*)(Ab + (size_t)lrow * K + k0 + lcol);
        float4 wv = *(const float4*)(Wb + (size_t)lrow * K + k0 + lcol);
        As[lcol + 0][lrow] = av.x; As[lcol + 1][lrow] = av.y;
        As[lcol + 2][lrow] = av.z; As[lcol + 3][lrow] = av.w;
        Bs[lcol + 0][lrow] = wv.x; Bs[lcol + 1][lrow] = wv.y;
        Bs[lcol + 2][lrow] = wv.z; Bs[lcol + 3][lrow] = wv.w;
        __syncthreads();
#pragma unroll
        for (int k = 0; k < 8; k++) {
            float4 a0 = *(const float4*)&As[k][ty * 8];
            float4 a1 = *(const float4*)&As[k][ty * 8 + 4];
            float4 b0 = *(const float4*)&Bs[k][tx * 8];
            float4 b1 = *(const float4*)&Bs[k][tx * 8 + 4];
            float ra[8] = {a0.x, a0.y, a0.z, a0.w, a1.x, a1.y, a1.z, a1.w};
            float rb[8] = {b0.x, b0.y, b0.z, b0.w, b1.x, b1.y, b1.z, b1.w};
#pragma unroll
            for (int i = 0; i < 8; i++)
#pragma unroll
                for (int j = 0; j < 8; j++) acc[i][j] += ra[i] * rb[j];
        }
        __syncthreads();
    }
    int col0 = blockIdx.x * 128 + tx * 8;
    float bb[8];
#pragma unroll
    for (int j = 0; j < 8; j++) bb[j] = bias[col0 + j];
#pragma unroll
    for (int i = 0; i < 8; i++) {
        int row = blockIdx.y * 128 + ty * 8 + i;
        float4 o0 = make_float4(acc[i][0] + bb[0], acc[i][1] + bb[1],
                                acc[i][2] + bb[2], acc[i][3] + bb[3]);
        float4 o1 = make_float4(acc[i][4] + bb[4], acc[i][5] + bb[5],
                                acc[i][6] + bb[6], acc[i][7] + bb[7]);
        *(float4*)(C + (size_t)row * N + col0) = o0;
        *(float4*)(C + (size_t)row * N + col0 + 4) = o1;
    }
}

__device__ __forceinline__ float sigmoidf(float x) { return 1.f / (1.f + expf(-x)); }

// ---------------- word BiLSTM persistent scan --------------------------------
// 128 CTAs: 64 per direction. CTA tile = 32 b x 32 n x 4 gates.
// Thread: 4 b (warp picks 4-row group), 1 n (lane), 4 gates. c stays in regs.
__global__ void __launch_bounds__(256) word_scan_kernel() {
    int cta = blockIdx.x;
    int dir = cta & 1;
    int id = cta >> 1;                // 0..63
    int bt = id >> 3;                 // 0..7 (32 b each)
    int nt = id & 7;                  // 0..7 (32 n each)
    const float* gxp  = dir ? (g_big + GXR_OFF) : g_big;
    const float* whhT = dir ? g_whhTr : g_whhTf;

    int lane = threadIdx.x & 31;
    int wg   = threadIdx.x >> 5;
    int n = nt * 32 + lane;
    int b0 = bt * 32 + wg * 4;
    const float* wbase = whhT + n;

    __shared__ float h_s[32][HH];     // 32KB
    float c_reg[4] = {0.f, 0.f, 0.f, 0.f};

#pragma unroll
    for (int u = 0; u < 4; u++) g_hw[dir][0][b0 + u][n] = 0.f;
    grid_barrier(128);

    for (int t = 0; t < Tt; t++) {
        int tt = dir ? (Tt - 1 - t) : t;
        int rb = t & 1, wb = rb ^ 1;
        const float* hsrc = &g_hw[dir][rb][bt * 32][0];
        for (int idx = threadIdx.x; idx < 32 * HH / 4; idx += 256)
            ((float4*)&h_s[0][0])[idx] = ((const float4*)hsrc)[idx];
        __syncthreads();

        float acc[4][4];
#pragma unroll
        for (int u = 0; u < 4; u++) {
            const float* gp = gxp + ((size_t)(b0 + u) * Tt + tt) * G4 + n;
            acc[u][0] = gp[0];
            acc[u][1] = gp[HH];
            acc[u][2] = gp[2 * HH];
            acc[u][3] = gp[3 * HH];
        }
#pragma unroll 8
        for (int k = 0; k < HH; k++) {
            float w0 = wbase[k * G4];
            float w1 = wbase[k * G4 + HH];
            float w2 = wbase[k * G4 + 2 * HH];
            float w3 = wbase[k * G4 + 3 * HH];
#pragma unroll
            for (int u = 0; u < 4; u++) {
                float hv = h_s[wg * 4 + u][k];
                acc[u][0] += hv * w0;
                acc[u][1] += hv * w1;
                acc[u][2] += hv * w2;
                acc[u][3] += hv * w3;
            }
        }
#pragma unroll
        for (int u = 0; u < 4; u++) {
            float ig = sigmoidf(acc[u][0]);
            float fg = sigmoidf(acc[u][1]);
            float gg = tanhf(acc[u][2]);
            float og = sigmoidf(acc[u][3]);
            c_reg[u] = fg * c_reg[u] + ig * gg;
            float h = og * tanhf(c_reg[u]);
            g_hw[dir][wb][b0 + u][n] = h;
            g_hcat[((size_t)(b0 + u) * Tt + tt) * H2 + dir * HH + n] = h;
        }
        grid_barrier(128);
    }
}

// ---------------- sentence LSTM persistent scan -------------------------------
// 128 CTAs: tile = 32 b x 32 n x 4 gates, K=512. Only final hT needed (buf 0).
__global__ void __launch_bounds__(256) sent_scan_kernel() {
    extern __shared__ float h_s[];    // [32][512] = 64KB dynamic
    int cta = blockIdx.x;
    int bt = cta >> 4;                // 0..7
    int nt = cta & 15;                // 0..15
    int lane = threadIdx.x & 31;
    int wg   = threadIdx.x >> 5;
    int n = nt * 32 + lane;
    int b0 = bt * 32 + wg * 4;
    const float* gxs = g_big;
    const float* wbase = g_whhTs + n;
    float c_reg[4] = {0.f, 0.f, 0.f, 0.f};

#pragma unroll
    for (int u = 0; u < 4; u++) g_hs[0][b0 + u][n] = 0.f;
    grid_barrier(128);

    for (int t = 0; t < Tt; t++) {
        int rb = t & 1, wb = rb ^ 1;
        const float* hsrc = &g_hs[rb][bt * 32][0];
        for (int idx = threadIdx.x; idx < 32 * H2 / 4; idx += 256)
            ((float4*)h_s)[idx] = ((const float4*)hsrc)[idx];
        __syncthreads();

        float acc[4][4];
#pragma unroll
        for (int u = 0; u < 4; u++) {
            const float* gp = gxs + ((size_t)(b0 + u) * Tt + t) * G8 + n;
            acc[u][0] = gp[0];
            acc[u][1] = gp[H2];
            acc[u][2] = gp[2 * H2];
            acc[u][3] = gp[3 * H2];
        }
#pragma unroll 8
        for (int k = 0; k < H2; k++) {
            float w0 = wbase[k * G8];
            float w1 = wbase[k * G8 + H2];
            float w2 = wbase[k * G8 + 2 * H2];
            float w3 = wbase[k * G8 + 3 * H2];
#pragma unroll
            for (int u = 0; u < 4; u++) {
                float hv = h_s[(wg * 4 + u) * H2 + k];
                acc[u][0] += hv * w0;
                acc[u][1] += hv * w1;
                acc[u][2] += hv * w2;
                acc[u][3] += hv * w3;
            }
        }
#pragma unroll
        for (int u = 0; u < 4; u++) {
            float ig = sigmoidf(acc[u][0]);
            float fg = sigmoidf(acc[u][1]);
            float gg = tanhf(acc[u][2]);
            float og = sigmoidf(acc[u][3]);
            c_reg[u] = fg * c_reg[u] + ig * gg;
            float h = og * tanhf(c_reg[u]);
            g_hs[wb][b0 + u][n] = h;   // t=127 writes buf 0 -> hT
        }
        grid_barrier(128);
    }
}

// ---------------- emissions + CRF (single block) ------------------------------
__global__ void __launch_bounds__(256) crf_kernel(
    const int* __restrict__ y,
    const float* __restrict__ lin_w, const float* __restrict__ lin_b,
    const float* __restrict__ cstart, const float* __restrict__ cend,
    const float* __restrict__ ctrans, float* __restrict__ out)
{
    __shared__ float pool[NC * H2];   // 32KB: lin_w staging, later tr/alpha
    __shared__ float e[Bq][NC];       // 16KB
    int tid = threadIdx.x;

    // stage lin_w [16][512] into smem
    for (int idx = tid; idx < NC * H2 / 4; idx += 256)
        ((float4*)pool)[idx] = ((const float4*)lin_w)[idx];
    __syncthreads();

    // emissions: thread tid handles sentence s = tid (hT = g_hs[0])
    {
        const float* hrow = &g_hs[0][tid][0];
        float acc[NC];
#pragma unroll
        for (int c = 0; c < NC; c++) acc[c] = lin_b[c];
        for (int k = 0; k < H2; k += 4) {
            float4 hv = *(const float4*)(hrow + k);
#pragma unroll
            for (int c = 0; c < NC; c++) {
                const float* wr = pool + c * H2 + k;
                acc[c] += hv.x * wr[0] + hv.y * wr[1] + hv.z * wr[2] + hv.w * wr[3];
            }
        }
#pragma unroll
        for (int c = 0; c < NC; c++) e[tid][c] = acc[c];
    }
    __syncthreads();

    // repurpose pool: tr [16*16] at 0, alpha at 256, alpha2 at 288
    if (tid < NC * NC) pool[tid] = ctrans[tid];
    __syncthreads();
    float* tr = pool;
    float* alpha = pool + 256;
    float* alpha2 = pool + 288;

    if (tid < NC) alpha[tid] = cstart[tid] + e[0][tid];
    __syncthreads();

    if (tid < 32) {
        for (int s = 1; s < Bq; s++) {
            if (tid < NC) {
                int j = tid;
                float m = -1e30f;
#pragma unroll
                for (int i = 0; i < NC; i++) m = fmaxf(m, alpha[i] + tr[i * NC + j]);
                float sum = 0.f;
#pragma unroll
                for (int i = 0; i < NC; i++) sum += expf(alpha[i] + tr[i * NC + j] - m);
                alpha2[j] = m + logf(sum) + e[s][j];
            }
            __syncwarp();
            if (tid < NC) alpha[tid] = alpha2[tid];
            __syncwarp();
        }
    }
    __syncthreads();

    if (tid == 0) {
        int yprev = y[0];
        float num = cstart[yprev] + e[0][yprev];
        for (int s = 1; s < Bq; s++) {
            int ys = y[s];
            num += tr[yprev * NC + ys] + e[s][ys];
            yprev = ys;
        }
        num += cend[yprev];

        float m = -1e30f;
        for (int i = 0; i < NC; i++) m = fmaxf(m, alpha[i] + cend[i]);
        float sum = 0.f;
        for (int i = 0; i < NC; i++) sum += expf(alpha[i] + cend[i] - m);
        float denom = m + logf(sum);
        out[0] = num - denom;
    }
}

// ---------------- launch ------------------------------------------------------
extern "C" void kernel_launch(void* const* d_in, const int* in_sizes, int n_in,
                              void* d_out, int out_size)
{
    const float* x      = (const float*)d_in[0];
    const int*   y      = (const int*)  d_in[1];
    // d_in[2] = mask (unused by the reference math)
    const float* w_ih_f = (const float*)d_in[3];
    const float* w_hh_f = (const float*)d_in[4];
    const float* b_f    = (const float*)d_in[5];
    const float* w_ih_r = (const float*)d_in[6];
    const float* w_hh_r = (const float*)d_in[7];
    const float* b_r    = (const float*)d_in[8];
    const float* w_ih_s = (const float*)d_in[9];
    const float* w_hh_s = (const float*)d_in[10];
    const float* b_s    = (const float*)d_in[11];
    const float* lin_w  = (const float*)d_in[12];
    const float* lin_b  = (const float*)d_in[13];
    const float* cstart = (const float*)d_in[14];
    const float* cend   = (const float*)d_in[15];
    const float* ctrans = (const float*)d_in[16];
    float* out = (float*)d_out;

    float *gbig, *hcat, *wtf, *wtr, *wts;
    cudaGetSymbolAddress((void**)&gbig, g_big);
    cudaGetSymbolAddress((void**)&hcat, g_hcat);
    cudaGetSymbolAddress((void**)&wtf, g_whhTf);
    cudaGetSymbolAddress((void**)&wtr, g_whhTr);
    cudaGetSymbolAddress((void**)&wts, g_whhTs);

    cudaFuncSetAttribute(sent_scan_kernel,
                         cudaFuncAttributeMaxDynamicSharedMemorySize, 65536);

    // transpose recurrent weights: [J][K] -> [K][J]
    transpose_kernel<<<(G4 * HH + 255) / 256, 256>>>(w_hh_f, wtf, G4, HH);
    transpose_kernel<<<(G4 * HH + 255) / 256, 256>>>(w_hh_r, wtr, G4, HH);
    transpose_kernel<<<(G8 * H2 + 255) / 256, 256>>>(w_hh_s, wts, G8, H2);

    // input projections (bias fused)
    dim3 g1(G4 / 128, (Bq * Tt) / 128);
    sgemm_bias<<<g1, 256>>>(x, w_ih_f, b_f, gbig, Bq * Tt, G4, Ff);
    sgemm_bias<<<g1, 256>>>(x, w_ih_r, b_r, gbig + GXR_OFF, Bq * Tt, G4, Ff);

    // word BiLSTM scan -> g_hcat
    word_scan_kernel<<<128, 256>>>();

    // sentence input projection (reuses g_big as gx_s)
    dim3 g2(G8 / 128, (Bq * Tt) / 128);
    sgemm_bias<<<g2, 256>>>(hcat, w_ih_s, b_s, gbig, Bq * Tt, G8, H2);

    // sentence LSTM scan -> g_hs[0] = hT
    sent_scan_kernel<<<128, 256, 65536>>>();

    // emissions + CRF -> scalar
    crf_kernel<<<1, 256>>>(y, lin_w, lin_b, cstart, cend, ctrans, out);
}